// round 9
// baseline (speedup 1.0000x reference)
#include <cuda_runtime.h>
#include <cuda_bf16.h>
#include <math.h>
#include <stdint.h>

#define D 128
#define MAXN 50000

// ---------------- scratch ----------------
__device__ float g_h[MAXN * D];
__device__ float g_m[MAXN * D];
__device__ float g_agg[MAXN * D];
__device__ float g_gi[MAXN * 3 * D];
__device__ float g_gh[MAXN * 3 * D];
__device__ float g_wihT[D * 3 * D];   // [K=128][M=384]
__device__ float g_whhT[D * 3 * D];

// ---------------- weight transpose: WT[k][m] = W[m][k], W is [384,128] ----------------
__global__ void transpose_kernel(const float* __restrict__ W, float* __restrict__ WT) {
    int idx = blockIdx.x * blockDim.x + threadIdx.x;
    if (idx >= 3 * D * D) return;
    int m = idx / D;
    int k = idx % D;
    WT[(size_t)k * (3 * D) + m] = W[idx];
}

// ---------------- cp.async helpers ----------------
__device__ __forceinline__ void cp16(uint32_t dst, const void* src, int sz) {
    asm volatile("cp.async.cg.shared.global [%0], [%1], 16, %2;"
                 :: "r"(dst), "l"(src), "r"(sz));
}
#define CP_COMMIT() asm volatile("cp.async.commit_group;" ::: "memory")
#define CP_WAIT0()  asm volatile("cp.async.wait_group 0;" ::: "memory")

// ---------------- FFMA GEMM, cp.async double-buffered ----------------
// C[N x M] = A[N x 128] @ B[128 x M]; M multiple of 128.
// Tile 128x128, BK=16, 256 threads, 8x8 outputs/thread.
#define BK 16
#define LDA 20    // As row stride in floats (16 + 4 pad)

__global__ __launch_bounds__(256, 2)
void gemm128(const float* __restrict__ A, const float* __restrict__ B,
             float* __restrict__ C, int N, int M) {
    __shared__ float As[2][128][LDA];   // row-major slab: As[stg][row][k]
    __shared__ float Bs[2][BK][128];    // Bs[stg][k][n]

    int tid = threadIdx.x;
    int block_row = blockIdx.y * 128;
    int block_col = blockIdx.x * 128;

    // A staging: 128 rows x 16 floats; thread -> (row = tid>>1, half = tid&1)
    int aR = tid >> 1;
    int aH = (tid & 1) * 8;
    int aGr = block_row + aR;
    int aSz = (aGr < N) ? 16 : 0;
    const float* aSrc = A + (size_t)(aGr < N ? aGr : 0) * 128 + aH;
    // B staging: 16 rows x 128 floats; thread -> (row = tid>>4, col8 = (tid&15)*8)
    int bR = tid >> 4;
    int bC = (tid & 15) * 8;
    const float* bSrc = B + (size_t)bR * M + block_col + bC;

    uint32_t aDst0 = (uint32_t)__cvta_generic_to_shared(&As[0][aR][aH]);
    uint32_t aDst1 = (uint32_t)__cvta_generic_to_shared(&As[1][aR][aH]);
    uint32_t bDst0 = (uint32_t)__cvta_generic_to_shared(&Bs[0][bR][bC]);
    uint32_t bDst1 = (uint32_t)__cvta_generic_to_shared(&Bs[1][bR][bC]);

    int tr = (tid >> 4) * 4;
    int tc = (tid & 15) * 4;

    float acc[8][8];
#pragma unroll
    for (int i = 0; i < 8; i++)
#pragma unroll
        for (int j = 0; j < 8; j++) acc[i][j] = 0.0f;

    // prologue: stage 0
    cp16(aDst0, aSrc, aSz);
    cp16(aDst0 + 16, aSrc + 4, aSz);
    cp16(bDst0, bSrc, 16);
    cp16(bDst0 + 16, bSrc + 4, 16);
    CP_COMMIT();

#pragma unroll 1
    for (int s = 0; s < 8; s++) {
        int cur = s & 1;
        CP_WAIT0();
        __syncthreads();

        if (s < 7) {
            int k0 = (s + 1) * BK;
            uint32_t ad = cur ? aDst0 : aDst1;
            uint32_t bd = cur ? bDst0 : bDst1;
            cp16(ad, aSrc + k0, aSz);
            cp16(ad + 16, aSrc + k0 + 4, aSz);
            cp16(bd, bSrc + (size_t)k0 * M, 16);
            cp16(bd + 16, bSrc + (size_t)k0 * M + 4, 16);
            CP_COMMIT();
        }

        // compute on buffer cur
#pragma unroll
        for (int kq = 0; kq < 4; kq++) {
            float4 a[8];
#pragma unroll
            for (int i = 0; i < 4; i++) {
                a[i]     = *(const float4*)&As[cur][tr + i][kq * 4];
                a[i + 4] = *(const float4*)&As[cur][tr + 64 + i][kq * 4];
            }
#pragma unroll
            for (int kk = 0; kk < 4; kk++) {
                int k = kq * 4 + kk;
                float4 n0 = *(const float4*)&Bs[cur][k][tc];
                float4 n1 = *(const float4*)&Bs[cur][k][tc + 64];
                float rn[8] = {n0.x, n0.y, n0.z, n0.w, n1.x, n1.y, n1.z, n1.w};
#pragma unroll
                for (int i = 0; i < 8; i++) {
                    float rm = ((const float*)&a[i])[kk];
#pragma unroll
                    for (int j = 0; j < 8; j++)
                        acc[i][j] = fmaf(rm, rn[j], acc[i][j]);
                }
            }
        }
        __syncthreads();
    }

#pragma unroll
    for (int ii = 0; ii < 2; ii++) {
#pragma unroll
        for (int i = 0; i < 4; i++) {
            int row = block_row + tr + ii * 64 + i;
            if (row >= N) continue;
#pragma unroll
            for (int jj = 0; jj < 2; jj++) {
                int col = block_col + tc + jj * 64;
                float4 r;
                r.x = acc[ii * 4 + i][jj * 4 + 0];
                r.y = acc[ii * 4 + i][jj * 4 + 1];
                r.z = acc[ii * 4 + i][jj * 4 + 2];
                r.w = acc[ii * 4 + i][jj * 4 + 3];
                *(float4*)&C[(size_t)row * M + col] = r;
            }
        }
    }
}

// ---------------- gather: h = embed[node_ids]; also zero agg ----------------
__global__ void gather_kernel(const int* __restrict__ node_ids,
                              const float4* __restrict__ embed4,
                              float4* __restrict__ h4,
                              float4* __restrict__ agg4, int N) {
    int idx = blockIdx.x * blockDim.x + threadIdx.x;
    if (idx >= N * 32) return;
    int n = idx >> 5;
    int c = idx & 31;
    int id = node_ids[n];
    h4[(size_t)n * 32 + c] = embed4[(size_t)id * 32 + c];
    agg4[idx] = make_float4(0.f, 0.f, 0.f, 0.f);
}

// ---------------- edge scatter, 4 edges per warp (MLP=4) ----------------
#define RED4(P, V)                                                         \
    asm volatile("red.global.add.v4.f32 [%0], {%1, %2, %3, %4};"           \
                 :: "l"(P), "f"((V).x), "f"((V).y), "f"((V).z), "f"((V).w) \
                 : "memory")

__global__ void scatter_kernel(const float4* __restrict__ m4,
                               const int* __restrict__ src,
                               const int* __restrict__ dst,
                               float* __restrict__ agg, int E) {
    int w = blockIdx.x * (blockDim.x >> 5) + (threadIdx.x >> 5);
    int lane = threadIdx.x & 31;
    int e0 = w * 4;
    if (e0 >= E) return;
    if (e0 + 4 <= E) {
        int s0 = __ldg(src + e0 + 0), s1 = __ldg(src + e0 + 1);
        int s2 = __ldg(src + e0 + 2), s3 = __ldg(src + e0 + 3);
        int d0 = __ldg(dst + e0 + 0), d1 = __ldg(dst + e0 + 1);
        int d2 = __ldg(dst + e0 + 2), d3 = __ldg(dst + e0 + 3);
        float4 v0 = m4[(size_t)s0 * 32 + lane];
        float4 v1 = m4[(size_t)s1 * 32 + lane];
        float4 v2 = m4[(size_t)s2 * 32 + lane];
        float4 v3 = m4[(size_t)s3 * 32 + lane];
        RED4(agg + (size_t)d0 * D + lane * 4, v0);
        RED4(agg + (size_t)d1 * D + lane * 4, v1);
        RED4(agg + (size_t)d2 * D + lane * 4, v2);
        RED4(agg + (size_t)d3 * D + lane * 4, v3);
    } else {
        for (int e = e0; e < E; e++) {
            int s = __ldg(src + e);
            int d = __ldg(dst + e);
            float4 v = m4[(size_t)s * 32 + lane];
            RED4(agg + (size_t)d * D + lane * 4, v);
        }
    }
}

// ---------------- GRU gate fusion (biases folded); optionally zero agg ----------------
__global__ void gru_kernel(const float4* __restrict__ gi4,
                           const float4* __restrict__ gh4,
                           const float4* __restrict__ bih4,
                           const float4* __restrict__ bhh4,
                           float4* __restrict__ h4,
                           float4* __restrict__ agg4,
                           int total4, int zero_agg) {
    int idx = blockIdx.x * blockDim.x + threadIdx.x;
    if (idx >= total4) return;
    int n = idx >> 5;
    int c = idx & 31;
    const float4* gin = gi4 + (size_t)n * 96;
    const float4* ghn = gh4 + (size_t)n * 96;
    float4 ir = gin[c], iz = gin[c + 32], in_ = gin[c + 64];
    float4 hr = ghn[c], hz = ghn[c + 32], hn = ghn[c + 64];
    float4 bir = bih4[c], biz = bih4[c + 32], bin = bih4[c + 64];
    float4 bhr = bhh4[c], bhz = bhh4[c + 32], bhn = bhh4[c + 64];
    float4 h = h4[idx];
    float4 o;
#define GRU1(X)                                                                 \
    {                                                                           \
        float r = 1.0f / (1.0f + __expf(-(ir.X + bir.X + hr.X + bhr.X)));       \
        float z = 1.0f / (1.0f + __expf(-(iz.X + biz.X + hz.X + bhz.X)));       \
        float nn = tanhf(in_.X + bin.X + r * (hn.X + bhn.X));                   \
        o.X = (1.0f - z) * nn + z * h.X;                                        \
    }
    GRU1(x) GRU1(y) GRU1(z) GRU1(w)
#undef GRU1
    h4[idx] = o;
    if (zero_agg) agg4[idx] = make_float4(0.f, 0.f, 0.f, 0.f);
}

// ---------------- per-graph mean pool (batch sorted) ----------------
__device__ __forceinline__ int lower_bound_dev(const int* a, int n, int key) {
    int lo = 0, hi = n;
    while (lo < hi) {
        int mid = (lo + hi) >> 1;
        if (a[mid] < key) lo = mid + 1; else hi = mid;
    }
    return lo;
}

__global__ void pool_kernel(const float* __restrict__ h,
                            const int* __restrict__ batch,
                            float* __restrict__ out, int N) {
    int g = blockIdx.x;
    int tid = threadIdx.x;
    int sub = tid >> 7;
    int d = tid & 127;
    __shared__ int s_lo, s_hi;
    __shared__ float sbuf[4][128];
    if (tid == 0) {
        s_lo = lower_bound_dev(batch, N, g);
        s_hi = lower_bound_dev(batch, N, g + 1);
    }
    __syncthreads();
    int lo = s_lo, hi = s_hi;
    float acc = 0.0f;
    for (int n = lo + sub; n < hi; n += 4)
        acc += h[(size_t)n * D + d];
    sbuf[sub][d] = acc;
    __syncthreads();
    if (sub == 0) {
        float total = sbuf[0][d] + sbuf[1][d] + sbuf[2][d] + sbuf[3][d];
        float cnt = (float)(hi - lo);
        out[(size_t)g * D + d] = total / fmaxf(cnt, 1.0f);
    }
}

// ---------------- launch ----------------
extern "C" void kernel_launch(void* const* d_in, const int* in_sizes, int n_in,
                              void* d_out, int out_size) {
    const int* node_ids = (const int*)d_in[0];
    const int* edge_index = (const int*)d_in[1];
    const int* batch = (const int*)d_in[2];
    const float* embed = (const float*)d_in[4];
    const float* conv_w = (const float*)d_in[5];   // [2][K][M] — already B layout
    const float* w_ih = (const float*)d_in[6];
    const float* w_hh = (const float*)d_in[7];
    const float* b_ih = (const float*)d_in[8];
    const float* b_hh = (const float*)d_in[9];
    float* out = (float*)d_out;

    int N = in_sizes[0];
    int E = in_sizes[1] / 2;
    int G = out_size / D;
    const int* src = edge_index;
    const int* dst = edge_index + E;

    float *h, *m, *agg, *gi, *gh, *wihT, *whhT;
    cudaGetSymbolAddress((void**)&h, g_h);
    cudaGetSymbolAddress((void**)&m, g_m);
    cudaGetSymbolAddress((void**)&agg, g_agg);
    cudaGetSymbolAddress((void**)&gi, g_gi);
    cudaGetSymbolAddress((void**)&gh, g_gh);
    cudaGetSymbolAddress((void**)&wihT, g_wihT);
    cudaGetSymbolAddress((void**)&whhT, g_whhT);

    static cudaStream_t s2 = nullptr;
    static cudaEvent_t evF[2], evJ[2];
    if (!s2) {
        cudaStreamCreateWithFlags(&s2, cudaStreamNonBlocking);
        for (int i = 0; i < 2; i++) {
            cudaEventCreateWithFlags(&evF[i], cudaEventDisableTiming);
            cudaEventCreateWithFlags(&evJ[i], cudaEventDisableTiming);
        }
    }

    transpose_kernel<<<(3 * D * D + 255) / 256, 256>>>(w_ih, wihT);
    transpose_kernel<<<(3 * D * D + 255) / 256, 256>>>(w_hh, whhT);
    gather_kernel<<<(N * 32 + 255) / 256, 256>>>(node_ids, (const float4*)embed,
                                                 (float4*)h, (float4*)agg, N);

    int rowBlocks = (N + 127) / 128;   // 391

    for (int layer = 0; layer < 2; layer++) {
        // fork: gh = h @ w_hh^T on side stream
        cudaEventRecord(evF[layer], 0);
        cudaStreamWaitEvent(s2, evF[layer], 0);
        gemm128<<<dim3(3, rowBlocks), 256, 0, s2>>>(h, whhT, gh, N, 3 * D);
        cudaEventRecord(evJ[layer], s2);

        // main: m = h @ conv_w[layer]
        gemm128<<<dim3(1, rowBlocks), 256>>>(h, conv_w + (size_t)layer * D * D,
                                             m, N, D);

        // agg[dst] += m[src]  (overlaps gh GEMM)
        {
            int warps = (E + 3) / 4;
            int blocks = (warps + 7) / 8;
            scatter_kernel<<<blocks, 256>>>((const float4*)m, src, dst, agg, E);
        }

        // gi = agg @ w_ih^T
        gemm128<<<dim3(3, rowBlocks), 256>>>(agg, wihT, gi, N, 3 * D);

        // join gh, fuse gates
        cudaStreamWaitEvent(0, evJ[layer], 0);
        gru_kernel<<<(N * 32 + 255) / 256, 256>>>((const float4*)gi,
                                                  (const float4*)gh,
                                                  (const float4*)b_ih,
                                                  (const float4*)b_hh,
                                                  (float4*)h, (float4*)agg,
                                                  N * 32, layer == 0 ? 1 : 0);
    }

    pool_kernel<<<G, 512>>>(h, batch, out, N);
}

// round 10
// speedup vs baseline: 1.1388x; 1.1388x over previous
#include <cuda_runtime.h>
#include <cuda_bf16.h>
#include <math.h>
#include <stdint.h>

#define D 128
#define MAXN 50000

// ---------------- scratch ----------------
__device__ float g_h[MAXN * D];
__device__ float g_agg[MAXN * D];          // scatter-add of h over edges
__device__ float g_gi[MAXN * 3 * D];
__device__ float g_gh[MAXN * 3 * D];
__device__ float g_wihT[D * 3 * D];        // [K=128][M=384]
__device__ float g_whhT[D * 3 * D];
__device__ float g_wcomb[2 * D * 3 * D];   // conv_w[l] @ w_ihT : [128][384] per layer

// ---------------- weight transpose: WT[k][m] = W[m][k], W is [384,128] ----------------
__global__ void transpose_kernel(const float* __restrict__ W, float* __restrict__ WT) {
    int idx = blockIdx.x * blockDim.x + threadIdx.x;
    if (idx >= 3 * D * D) return;
    int m = idx / D;
    int k = idx % D;
    WT[(size_t)k * (3 * D) + m] = W[idx];
}

// ---------------- FFMA register-blocked GEMM (proven R8 version) ----------------
// C[N x M] = A[N x 128] @ B[128 x M]; M multiple of 128.
#define BK 16
__global__ __launch_bounds__(256, 2)
void gemm128(const float* __restrict__ A, const float* __restrict__ B,
             float* __restrict__ C, int N, int M) {
    __shared__ float As[BK][132];   // transposed As[k][m]
    __shared__ float Bs[BK][128];   // Bs[k][n]

    int tid = threadIdx.x;
    int block_row = blockIdx.y * 128;
    int block_col = blockIdx.x * 128;

    int aRow = tid >> 2;
    int aCol = (tid & 3) * 4;
    int bRow = tid >> 5;
    int bCol = (tid & 31) * 4;
    int tr = (tid >> 4) * 4;
    int tc = (tid & 15) * 4;

    float acc[8][8];
#pragma unroll
    for (int i = 0; i < 8; i++)
#pragma unroll
        for (int j = 0; j < 8; j++) acc[i][j] = 0.0f;

    for (int k0 = 0; k0 < 128; k0 += BK) {
#pragma unroll
        for (int p = 0; p < 2; p++) {
            int r = aRow + p * 64;
            int gr = block_row + r;
            float4 v = make_float4(0.f, 0.f, 0.f, 0.f);
            if (gr < N) v = *(const float4*)(A + (size_t)gr * 128 + k0 + aCol);
            As[aCol + 0][r] = v.x;
            As[aCol + 1][r] = v.y;
            As[aCol + 2][r] = v.z;
            As[aCol + 3][r] = v.w;
        }
#pragma unroll
        for (int p = 0; p < 2; p++) {
            int r = bRow + p * 8;
            float4 v = *(const float4*)(B + (size_t)(k0 + r) * M + block_col + bCol);
            *(float4*)&Bs[r][bCol] = v;
        }
        __syncthreads();

#pragma unroll
        for (int k = 0; k < BK; k++) {
            float4 m0 = *(const float4*)&As[k][tr];
            float4 m1 = *(const float4*)&As[k][tr + 64];
            float4 n0 = *(const float4*)&Bs[k][tc];
            float4 n1 = *(const float4*)&Bs[k][tc + 64];
            float rm[8] = {m0.x, m0.y, m0.z, m0.w, m1.x, m1.y, m1.z, m1.w};
            float rn[8] = {n0.x, n0.y, n0.z, n0.w, n1.x, n1.y, n1.z, n1.w};
#pragma unroll
            for (int i = 0; i < 8; i++)
#pragma unroll
                for (int j = 0; j < 8; j++)
                    acc[i][j] = fmaf(rm[i], rn[j], acc[i][j]);
        }
        __syncthreads();
    }

#pragma unroll
    for (int ii = 0; ii < 2; ii++) {
#pragma unroll
        for (int i = 0; i < 4; i++) {
            int row = block_row + tr + ii * 64 + i;
            if (row >= N) continue;
#pragma unroll
            for (int jj = 0; jj < 2; jj++) {
                int col = block_col + tc + jj * 64;
                float4 r;
                r.x = acc[ii * 4 + i][jj * 4 + 0];
                r.y = acc[ii * 4 + i][jj * 4 + 1];
                r.z = acc[ii * 4 + i][jj * 4 + 2];
                r.w = acc[ii * 4 + i][jj * 4 + 3];
                *(float4*)&C[(size_t)row * M + col] = r;
            }
        }
    }
}

// ---------------- gather: h = embed[node_ids]; also zero agg ----------------
__global__ void gather_kernel(const int* __restrict__ node_ids,
                              const float4* __restrict__ embed4,
                              float4* __restrict__ h4,
                              float4* __restrict__ agg4, int N) {
    int idx = blockIdx.x * blockDim.x + threadIdx.x;
    if (idx >= N * 32) return;
    int n = idx >> 5;
    int c = idx & 31;
    int id = node_ids[n];
    h4[(size_t)n * 32 + c] = embed4[(size_t)id * 32 + c];
    agg4[idx] = make_float4(0.f, 0.f, 0.f, 0.f);
}

// ---------------- edge scatter: agg[dst] += h[src], 4 edges/warp ----------------
#define RED4(P, V)                                                         \
    asm volatile("red.global.add.v4.f32 [%0], {%1, %2, %3, %4};"           \
                 :: "l"(P), "f"((V).x), "f"((V).y), "f"((V).z), "f"((V).w) \
                 : "memory")

__global__ void scatter_kernel(const float4* __restrict__ h4,
                               const int* __restrict__ src,
                               const int* __restrict__ dst,
                               float* __restrict__ agg, int E) {
    int w = blockIdx.x * (blockDim.x >> 5) + (threadIdx.x >> 5);
    int lane = threadIdx.x & 31;
    int e0 = w * 4;
    if (e0 >= E) return;
    if (e0 + 4 <= E) {
        int s0 = __ldg(src + e0 + 0), s1 = __ldg(src + e0 + 1);
        int s2 = __ldg(src + e0 + 2), s3 = __ldg(src + e0 + 3);
        int d0 = __ldg(dst + e0 + 0), d1 = __ldg(dst + e0 + 1);
        int d2 = __ldg(dst + e0 + 2), d3 = __ldg(dst + e0 + 3);
        float4 v0 = h4[(size_t)s0 * 32 + lane];
        float4 v1 = h4[(size_t)s1 * 32 + lane];
        float4 v2 = h4[(size_t)s2 * 32 + lane];
        float4 v3 = h4[(size_t)s3 * 32 + lane];
        RED4(agg + (size_t)d0 * D + lane * 4, v0);
        RED4(agg + (size_t)d1 * D + lane * 4, v1);
        RED4(agg + (size_t)d2 * D + lane * 4, v2);
        RED4(agg + (size_t)d3 * D + lane * 4, v3);
    } else {
        for (int e = e0; e < E; e++) {
            int s = __ldg(src + e);
            int d = __ldg(dst + e);
            float4 v = h4[(size_t)s * 32 + lane];
            RED4(agg + (size_t)d * D + lane * 4, v);
        }
    }
}

// ---------------- GRU gate fusion (biases folded); optionally zero agg ----------------
__global__ void gru_kernel(const float4* __restrict__ gi4,
                           const float4* __restrict__ gh4,
                           const float4* __restrict__ bih4,
                           const float4* __restrict__ bhh4,
                           float4* __restrict__ h4,
                           float4* __restrict__ agg4,
                           int total4, int zero_agg) {
    int idx = blockIdx.x * blockDim.x + threadIdx.x;
    if (idx >= total4) return;
    int n = idx >> 5;
    int c = idx & 31;
    const float4* gin = gi4 + (size_t)n * 96;
    const float4* ghn = gh4 + (size_t)n * 96;
    float4 ir = gin[c], iz = gin[c + 32], in_ = gin[c + 64];
    float4 hr = ghn[c], hz = ghn[c + 32], hn = ghn[c + 64];
    float4 bir = bih4[c], biz = bih4[c + 32], bin = bih4[c + 64];
    float4 bhr = bhh4[c], bhz = bhh4[c + 32], bhn = bhh4[c + 64];
    float4 h = h4[idx];
    float4 o;
#define GRU1(X)                                                                 \
    {                                                                           \
        float r = 1.0f / (1.0f + __expf(-(ir.X + bir.X + hr.X + bhr.X)));       \
        float z = 1.0f / (1.0f + __expf(-(iz.X + biz.X + hz.X + bhz.X)));       \
        float nn = tanhf(in_.X + bin.X + r * (hn.X + bhn.X));                   \
        o.X = (1.0f - z) * nn + z * h.X;                                        \
    }
    GRU1(x) GRU1(y) GRU1(z) GRU1(w)
#undef GRU1
    h4[idx] = o;
    if (zero_agg) agg4[idx] = make_float4(0.f, 0.f, 0.f, 0.f);
}

// ---------------- per-graph mean pool (batch sorted) ----------------
__device__ __forceinline__ int lower_bound_dev(const int* a, int n, int key) {
    int lo = 0, hi = n;
    while (lo < hi) {
        int mid = (lo + hi) >> 1;
        if (a[mid] < key) lo = mid + 1; else hi = mid;
    }
    return lo;
}

__global__ void pool_kernel(const float* __restrict__ h,
                            const int* __restrict__ batch,
                            float* __restrict__ out, int N) {
    int g = blockIdx.x;
    int tid = threadIdx.x;
    int sub = tid >> 7;
    int d = tid & 127;
    __shared__ int s_lo, s_hi;
    __shared__ float sbuf[4][128];
    if (tid == 0) {
        s_lo = lower_bound_dev(batch, N, g);
        s_hi = lower_bound_dev(batch, N, g + 1);
    }
    __syncthreads();
    int lo = s_lo, hi = s_hi;
    float acc = 0.0f;
    for (int n = lo + sub; n < hi; n += 4)
        acc += h[(size_t)n * D + d];
    sbuf[sub][d] = acc;
    __syncthreads();
    if (sub == 0) {
        float total = sbuf[0][d] + sbuf[1][d] + sbuf[2][d] + sbuf[3][d];
        float cnt = (float)(hi - lo);
        out[(size_t)g * D + d] = total / fmaxf(cnt, 1.0f);
    }
}

// ---------------- launch ----------------
extern "C" void kernel_launch(void* const* d_in, const int* in_sizes, int n_in,
                              void* d_out, int out_size) {
    const int* node_ids = (const int*)d_in[0];
    const int* edge_index = (const int*)d_in[1];
    const int* batch = (const int*)d_in[2];
    const float* embed = (const float*)d_in[4];
    const float* conv_w = (const float*)d_in[5];   // [2][K=128][M=128]
    const float* w_ih = (const float*)d_in[6];
    const float* w_hh = (const float*)d_in[7];
    const float* b_ih = (const float*)d_in[8];
    const float* b_hh = (const float*)d_in[9];
    float* out = (float*)d_out;

    int N = in_sizes[0];
    int E = in_sizes[1] / 2;
    int G = out_size / D;
    const int* src = edge_index;
    const int* dst = edge_index + E;

    float *h, *agg, *gi, *gh, *wihT, *whhT, *wcomb;
    cudaGetSymbolAddress((void**)&h, g_h);
    cudaGetSymbolAddress((void**)&agg, g_agg);
    cudaGetSymbolAddress((void**)&gi, g_gi);
    cudaGetSymbolAddress((void**)&gh, g_gh);
    cudaGetSymbolAddress((void**)&wihT, g_wihT);
    cudaGetSymbolAddress((void**)&whhT, g_whhT);
    cudaGetSymbolAddress((void**)&wcomb, g_wcomb);

    static cudaStream_t s2 = nullptr;
    static cudaEvent_t evF[2], evJ[2], evP;
    if (!s2) {
        cudaStreamCreateWithFlags(&s2, cudaStreamNonBlocking);
        for (int i = 0; i < 2; i++) {
            cudaEventCreateWithFlags(&evF[i], cudaEventDisableTiming);
            cudaEventCreateWithFlags(&evJ[i], cudaEventDisableTiming);
        }
        cudaEventCreateWithFlags(&evP, cudaEventDisableTiming);
    }

    // ---- prep: transposes + combined weights (Wcomb[l] = conv_w[l] @ w_ihT) ----
    transpose_kernel<<<(3 * D * D + 255) / 256, 256>>>(w_ih, wihT);
    transpose_kernel<<<(3 * D * D + 255) / 256, 256>>>(w_hh, whhT);
    // Wcomb on side stream (overlaps gather); they depend on wihT
    cudaEventRecord(evP, 0);
    cudaStreamWaitEvent(s2, evP, 0);
    gemm128<<<dim3(3, 1), 256, 0, s2>>>(conv_w, wihT, wcomb, D, 3 * D);
    gemm128<<<dim3(3, 1), 256, 0, s2>>>(conv_w + (size_t)D * D, wihT,
                                        wcomb + (size_t)D * 3 * D, D, 3 * D);
    cudaEventRecord(evJ[1], s2);  // reuse; re-recorded below per layer

    gather_kernel<<<(N * 32 + 255) / 256, 256>>>(node_ids, (const float4*)embed,
                                                 (float4*)h, (float4*)agg, N);
    cudaStreamWaitEvent(0, evJ[1], 0);   // ensure wcomb ready before layer 0 gi

    int rowBlocks = (N + 127) / 128;   // 391

    for (int layer = 0; layer < 2; layer++) {
        // fork: gh = h @ w_hh^T on side stream (overlaps scatter on main)
        cudaEventRecord(evF[layer], 0);
        cudaStreamWaitEvent(s2, evF[layer], 0);
        gemm128<<<dim3(3, rowBlocks), 256, 0, s2>>>(h, whhT, gh, N, 3 * D);
        cudaEventRecord(evJ[layer], s2);

        // main: agg[dst] += h[src]
        {
            int warps = (E + 3) / 4;
            int blocks = (warps + 7) / 8;
            scatter_kernel<<<blocks, 256>>>((const float4*)h, src, dst, agg, E);
        }

        // gi = agg @ Wcomb[layer]   (= ((S h) @ conv_w) @ w_ih^T)
        gemm128<<<dim3(3, rowBlocks), 256>>>(agg, wcomb + (size_t)layer * D * 3 * D,
                                             gi, N, 3 * D);

        // join gh, fuse gates; zero agg for next layer's scatter
        cudaStreamWaitEvent(0, evJ[layer], 0);
        gru_kernel<<<(N * 32 + 255) / 256, 256>>>((const float4*)gi,
                                                  (const float4*)gh,
                                                  (const float4*)b_ih,
                                                  (const float4*)b_hh,
                                                  (float4*)h, (float4*)agg,
                                                  N * 32, layer == 0 ? 1 : 0);
    }

    pool_kernel<<<G, 512>>>(h, batch, out, N);
}